// round 6
// baseline (speedup 1.0000x reference)
#include <cuda_runtime.h>
#include <cuda_fp16.h>

#define N_NODES 100000
#define N_EDGES 1600000
#define D 64
#define SCAN_BLK 512
#define NPART ((N_NODES + SCAN_BLK - 1) / SCAN_BLK)   // 196

// ---------------- packed f32x2 helpers (sm_103a) ------------------------------
#define PACK2(dst, lo, hi) \
    asm("mov.b64 %0, {%1, %2};" : "=l"(dst) : "f"(lo), "f"(hi))
#define UNPACK2(lo, hi, src) \
    asm("mov.b64 {%0, %1}, %2;" : "=f"(lo), "=f"(hi) : "l"(src))
#define FMA2(acc, a, b) \
    asm("fma.rn.f32x2 %0, %1, %2, %0;" : "+l"(acc) : "l"(a), "l"(b))

// ---------------- scratch (device globals; no allocation allowed) -------------
// INVARIANT: g_cnt == 0 and g_ticket == 0 at every kernel_launch entry.
__device__ __align__(16)  int   g_cnt[N_NODES];
__device__ __align__(16)  float g_dinv[N_NODES];
__device__ __align__(16)  int2  g_e2 [N_EDGES];       // compacted (src,dst)
__device__ __align__(16)  int2  g_csr[N_EDGES];       // (src, coeff) grouped by dst
__device__ __align__(16)  int   g_off[N_NODES];       // block-LOCAL exclusive scan
__device__ __align__(16)  int   g_end[N_NODES];       // block-LOCAL inclusive scan
__device__ __align__(16)  int   g_part[SCAN_BLK];     // scanned per-block partials
__device__ __align__(128) uint4 g_xh [N_NODES * 8];   // x as fp16, row = 128B
__device__ __align__(128) uint4 g_h1h[N_NODES * 8];   // hop-1 result, fp16
__device__ __align__(128) float g_h2 [N_NODES * D];   // hop-2 result, fp32
__device__ int g_ticket;                              // self-resetting

// ---------------- 1: dtype probe + x->fp16 + edge compaction + histogram ------
__global__ void k_init(const unsigned int* __restrict__ ei_u32,
                       const void* __restrict__ eiv,
                       const float2* __restrict__ x2) {
    __shared__ int s_is64;
    if (threadIdx.x < 32) {
        // int64 values < 2^31 => high words all zero; int32 misread => random.
        unsigned hi = ei_u32[2 * threadIdx.x + 1];
        unsigned ball = __ballot_sync(0xffffffffu, hi != 0u);
        if (threadIdx.x == 0) s_is64 = (ball == 0u);
    }
    __syncthreads();
    int t = blockIdx.x * blockDim.x + threadIdx.x;
    if (t < N_NODES * 32) {
        float2 v = __ldg(&x2[t]);
        ((__half2*)g_xh)[t] = __floats2half2_rn(v.x, v.y);
    }
    if (t < N_EDGES) {
        int s, d;
        if (s_is64) {
            const long long* p = (const long long*)eiv;
            s = (int)p[t];
            d = (int)p[N_EDGES + t];
        } else {
            const int* p = (const int*)eiv;
            s = p[t];
            d = p[N_EDGES + t];
        }
        g_e2[t] = make_int2(s, d);
        atomicAdd(&g_cnt[d], 1);   // g_cnt pre-zeroed (invariant)
    }
}

// ---------------- 2: dinv + block scan + last-block partial scan --------------
// Also re-zeroes g_cnt so k_fill can use it as a cursor.
__global__ void k_scan_local() {
    __shared__ int s[SCAN_BLK];
    __shared__ int lastFlag;
    int tid = threadIdx.x;
    int i = blockIdx.x * SCAN_BLK + tid;
    int v = (i < N_NODES) ? g_cnt[i] : 0;
    if (i < N_NODES) {
        g_dinv[i] = rsqrtf((float)(v + 1));   // +1 self-loop
        g_cnt[i] = 0;
    }
    s[tid] = v;
    __syncthreads();
    for (int off = 1; off < SCAN_BLK; off <<= 1) {
        int t2 = (tid >= off) ? s[tid - off] : 0;
        __syncthreads();
        s[tid] += t2;
        __syncthreads();
    }
    if (i < N_NODES) { g_end[i] = s[tid]; g_off[i] = s[tid] - v; }  // block-local
    if (tid == SCAN_BLK - 1) g_part[blockIdx.x] = s[tid];
    __threadfence();
    if (tid == 0)
        lastFlag = (atomicAdd(&g_ticket, 1) == (int)gridDim.x - 1);
    __syncthreads();
    if (lastFlag) {  // last-arriving block scans the partials
        int p = (tid < NPART) ? *((volatile int*)&g_part[tid]) : 0;
        s[tid] = p;
        __syncthreads();
        for (int off = 1; off < SCAN_BLK; off <<= 1) {
            int t2 = (tid >= off) ? s[tid - off] : 0;
            __syncthreads();
            s[tid] += t2;
            __syncthreads();
        }
        if (tid < NPART) g_part[tid] = s[tid];
        if (tid == 0) g_ticket = 0;            // restore invariant
    }
}

// ---------------- 3: CSR fill; prefix applied inline; g_cnt as cursor ---------
__global__ void k_fill() {
    int e = blockIdx.x * blockDim.x + threadIdx.x;
    if (e >= N_EDGES) return;
    int2 sd = __ldg(&g_e2[e]);
    int s = sd.x, d = sd.y;
    float c = g_dinv[s] * g_dinv[d];
    int blk = d >> 9;                          // SCAN_BLK = 512
    int add = (blk > 0) ? g_part[blk - 1] : 0;
    int pos = g_off[d] + add + atomicAdd(&g_cnt[d], 1);
    g_csr[pos] = make_int2(s, __float_as_int(c));
}

// ---------------- 4/5: hop: 8 lanes/row, 4 edges in flight per warp -----------
// Lane owns 8 features (uint4 of 4 half2). Quarter-warp eq = lane>>3 processes
// edge i+eq; partial sums combined with shfl_xor(8) + shfl_xor(16).
template <bool OUT_HALF>
__global__ void k_hop(const uint4* __restrict__ in, void* __restrict__ outv) {
    int warp = (blockIdx.x * blockDim.x + threadIdx.x) >> 5;
    if (warp >= N_NODES) return;
    int lane = threadIdx.x & 31;
    int fl   = lane & 7;         // 16B slot within the 128B row
    int eq   = lane >> 3;        // which edge of the quad (0..3)

    int blk = warp >> 9;
    int add = (blk > 0) ? g_part[blk - 1] : 0;
    int beg = g_off[warp] + add;
    int end = g_end[warp] + add;
    float di = g_dinv[warp];
    float sl = di * di;          // self-loop coefficient

    float2 acc[4];
    if (eq == 0) {               // self-loop term, counted once
        uint4 rs = __ldg(&in[warp * 8 + fl]);
        const __half2* h = reinterpret_cast<const __half2*>(&rs);
        #pragma unroll
        for (int q = 0; q < 4; q++) {
            float2 v = __half22float2(h[q]);
            acc[q] = make_float2(sl * v.x, sl * v.y);
        }
    } else {
        #pragma unroll
        for (int q = 0; q < 4; q++) acc[q] = make_float2(0.f, 0.f);
    }

    for (int j = beg; j < end; j += 32) {
        int m = end - j; if (m > 32) m = 32;
        int2 md = make_int2(0, 0);
        if (lane < m) md = __ldg(&g_csr[j + lane]);
        #pragma unroll 2
        for (int i = 0; i < m; i += 4) {
            int idx = i + eq;    // lanes past m hold md=(0,0) -> ci=0, harmless
            int   si = __shfl_sync(0xffffffffu, md.x, idx);
            float ci = __int_as_float(__shfl_sync(0xffffffffu, md.y, idx));
            uint4 r = __ldg(&in[si * 8 + fl]);
            const __half2* h = reinterpret_cast<const __half2*>(&r);
            #pragma unroll
            for (int q = 0; q < 4; q++) {
                float2 v = __half22float2(h[q]);
                acc[q].x = fmaf(ci, v.x, acc[q].x);
                acc[q].y = fmaf(ci, v.y, acc[q].y);
            }
        }
    }
    #pragma unroll
    for (int q = 0; q < 4; q++) {
        acc[q].x += __shfl_xor_sync(0xffffffffu, acc[q].x, 8);
        acc[q].y += __shfl_xor_sync(0xffffffffu, acc[q].y, 8);
        acc[q].x += __shfl_xor_sync(0xffffffffu, acc[q].x, 16);
        acc[q].y += __shfl_xor_sync(0xffffffffu, acc[q].y, 16);
    }
    if (eq == 0) {
        if (OUT_HALF) {
            uint4 o;
            __half2* oh = reinterpret_cast<__half2*>(&o);
            #pragma unroll
            for (int q = 0; q < 4; q++) oh[q] = __floats2half2_rn(acc[q].x, acc[q].y);
            ((uint4*)outv)[warp * 8 + fl] = o;
        } else {
            ((float4*)outv)[warp * 16 + fl * 2] =
                make_float4(acc[0].x, acc[0].y, acc[1].x, acc[1].y);
            ((float4*)outv)[warp * 16 + fl * 2 + 1] =
                make_float4(acc[2].x, acc[2].y, acc[3].x, acc[3].y);
        }
    }
    if (OUT_HALF && lane == 0) g_cnt[warp] = 0;   // restore invariant after fill
}

// ---------------- 6: out = relu(h2 @ W^T + b), packed f32x2 FMA ---------------
__global__ void __launch_bounds__(128) k_linear_relu(
        const float* __restrict__ h, const float* __restrict__ W,
        const float* __restrict__ b, float* __restrict__ out) {
    __shared__ float4 Ws4[D * 16];   // W[o][k] as float4 over k
    __shared__ float bs[D];
    for (int i = threadIdx.x; i < D * 16; i += blockDim.x)
        Ws4[i] = ((const float4*)W)[i];
    for (int i = threadIdx.x; i < D; i += blockDim.x) bs[i] = b[i];
    __syncthreads();

    int n = blockIdx.x * blockDim.x + threadIdx.x;
    if (n >= N_NODES) return;

    unsigned long long acc[D];
    #pragma unroll
    for (int o = 0; o < D; o++) PACK2(acc[o], bs[o], 0.0f);

    const float4* hr = (const float4*)(h + n * D);
    #pragma unroll 2
    for (int k4 = 0; k4 < 16; k4++) {
        float4 hv = hr[k4];
        unsigned long long h01, h23;
        PACK2(h01, hv.x, hv.y);
        PACK2(h23, hv.z, hv.w);
        #pragma unroll
        for (int o = 0; o < D; o++) {
            float4 w = Ws4[o * 16 + k4];
            unsigned long long w01, w23;
            PACK2(w01, w.x, w.y);
            PACK2(w23, w.z, w.w);
            FMA2(acc[o], h01, w01);
            FMA2(acc[o], h23, w23);
        }
    }
    float* orow = out + n * D;
    #pragma unroll
    for (int o = 0; o < D; o++) {
        float lo, hi;
        UNPACK2(lo, hi, acc[o]);
        orow[o] = fmaxf(lo + hi, 0.0f);
    }
}

// ---------------- launch ------------------------------------------------------
extern "C" void kernel_launch(void* const* d_in, const int* in_sizes, int n_in,
                              void* d_out, int out_size) {
    const float* x  = (const float*)d_in[0];   // [N, 64]
    const float* W  = (const float*)d_in[1];   // [64, 64]
    const float* b  = (const float*)d_in[2];   // [64]
    const void*  ei = d_in[3];                 // [2, E] int32 or int64
    float* out = (float*)d_out;                // [N, 64]

    void *xhp = nullptr, *h1p = nullptr, *h2p = nullptr;
    cudaGetSymbolAddress(&xhp, g_xh);
    cudaGetSymbolAddress(&h1p, g_h1h);
    cudaGetSymbolAddress(&h2p, g_h2);

    const int TB = 256;
    const int gBig = (N_NODES * 32 + TB - 1) / TB;   // 3.2M threads
    const int gE   = (N_EDGES + TB - 1) / TB;
    const int gLin = (N_NODES + 127) / 128;

    k_init      <<<gBig, TB>>>((const unsigned int*)ei, ei, (const float2*)x);
    k_scan_local<<<NPART, SCAN_BLK>>>();
    k_fill      <<<gE, TB>>>();

    // two hops: xh -> h1h (fp16) -> h2 (fp32); pure gather, no atomics
    k_hop<true> <<<gBig, TB>>>((const uint4*)xhp, h1p);
    k_hop<false><<<gBig, TB>>>((const uint4*)h1p, h2p);

    // out = relu(h2 @ W^T + b)
    k_linear_relu<<<gLin, 128>>>((const float*)h2p, W, b, out);
}

// round 7
// speedup vs baseline: 1.6463x; 1.6463x over previous
#include <cuda_runtime.h>
#include <cuda_fp16.h>

#define N_NODES 100000
#define N_EDGES 1600000
#define D 64
#define SCAN_BLK 512
#define NPART ((N_NODES + SCAN_BLK - 1) / SCAN_BLK)   // 196

// ---------------- packed f32x2 helpers (sm_103a) ------------------------------
#define PACK2(dst, lo, hi) \
    asm("mov.b64 %0, {%1, %2};" : "=l"(dst) : "f"(lo), "f"(hi))
#define UNPACK2(lo, hi, src) \
    asm("mov.b64 {%0, %1}, %2;" : "=f"(lo), "=f"(hi) : "l"(src))
#define FMA2(acc, a, b) \
    asm("fma.rn.f32x2 %0, %1, %2, %0;" : "+l"(acc) : "l"(a), "l"(b))

// ---------------- scratch (device globals; no allocation allowed) -------------
__device__ __align__(16)  int   g_cnt[N_NODES];      // re-zeroed every run
__device__ __align__(16)  float g_dinv[N_NODES];
__device__ __align__(16)  int2  g_csr[N_EDGES];      // (src, coeff) grouped by dst
__device__ __align__(16)  int   g_off[N_NODES];      // CSR row start (absolute)
__device__ __align__(16)  int   g_end[N_NODES];      // CSR row end   (absolute)
__device__ __align__(16)  int   g_cursor[N_NODES];   // fill cursors
__device__ __align__(16)  int   g_part[SCAN_BLK];    // scanned per-block partials
__device__ __align__(128) uint2 g_xh [N_NODES * 16]; // x as fp16 (row = 128B)
__device__ __align__(128) uint2 g_h1h[N_NODES * 16]; // hop-1 result, fp16
__device__ __align__(128) float g_h2 [N_NODES * D];  // hop-2 result, fp32
__device__ int g_is64;
__device__ int g_ticket;                             // self-resetting

// ---------------- dtype-adaptive edge loader ----------------------------------
__device__ __forceinline__ void load_edge(const void* __restrict__ eiv, int e,
                                          int& s, int& d) {
    if (g_is64) {
        const long long* p = (const long long*)eiv;
        s = (int)p[e];
        d = (int)p[N_EDGES + e];
    } else {
        const int* p = (const int*)eiv;
        s = p[e];
        d = p[N_EDGES + e];
    }
}

// ---------------- 1: zero counts + dtype probe + x -> fp16 --------------------
__global__ void k_init(const unsigned int* __restrict__ ei_u32,
                       const float2* __restrict__ x2) {
    int t = blockIdx.x * blockDim.x + threadIdx.x;
    if (t < N_NODES * 32) {
        float2 v = __ldg(&x2[t]);
        ((__half2*)g_xh)[t] = __floats2half2_rn(v.x, v.y);
    }
    if (t < N_NODES) g_cnt[t] = 0;
    if (t == 0) {
        // int64 values < 2^31 => high words all zero; int32 misread => random.
        int is64 = 1;
        for (int k = 0; k < 256; k++)
            if (ei_u32[2 * k + 1] != 0u) { is64 = 0; break; }
        g_is64 = is64;
    }
}

// ---------------- 2: in-degree histogram --------------------------------------
__global__ void k_pass1(const void* __restrict__ eiv) {
    int e = blockIdx.x * blockDim.x + threadIdx.x;
    if (e >= N_EDGES) return;
    int s, d;
    load_edge(eiv, e, s, d);
    atomicAdd(&g_cnt[d], 1);
}

// ---------------- 3: dinv + block scan + last-block partial scan --------------
__global__ void k_scan_local() {
    __shared__ int s[SCAN_BLK];
    __shared__ int lastFlag;
    int tid = threadIdx.x;
    int i = blockIdx.x * SCAN_BLK + tid;
    int v = (i < N_NODES) ? g_cnt[i] : 0;
    if (i < N_NODES) {
        g_dinv[i] = rsqrtf((float)(v + 1));   // +1 self-loop
        g_cnt[i] = 0;                          // restore for next graph replay
    }
    s[tid] = v;
    __syncthreads();
    for (int off = 1; off < SCAN_BLK; off <<= 1) {
        int t2 = (tid >= off) ? s[tid - off] : 0;
        __syncthreads();
        s[tid] += t2;
        __syncthreads();
    }
    if (i < N_NODES) { g_end[i] = s[tid]; g_off[i] = s[tid] - v; }  // block-local
    if (tid == SCAN_BLK - 1) g_part[blockIdx.x] = s[tid];
    __threadfence();
    if (tid == 0)
        lastFlag = (atomicAdd(&g_ticket, 1) == (int)gridDim.x - 1);
    __syncthreads();
    if (lastFlag) {  // last-arriving block scans the partials
        int p = (tid < NPART) ? *((volatile int*)&g_part[tid]) : 0;
        s[tid] = p;
        __syncthreads();
        for (int off = 1; off < SCAN_BLK; off <<= 1) {
            int t2 = (tid >= off) ? s[tid - off] : 0;
            __syncthreads();
            s[tid] += t2;
            __syncthreads();
        }
        if (tid < NPART) g_part[tid] = s[tid];
        if (tid == 0) g_ticket = 0;            // restore for next replay
    }
}

// ---------------- 4: apply block prefix ---------------------------------------
__global__ void k_finalize() {
    int i = blockIdx.x * blockDim.x + threadIdx.x;
    if (i >= N_NODES) return;
    int p = i >> 9;                            // SCAN_BLK = 512
    int add = (p > 0) ? g_part[p - 1] : 0;
    int excl = g_off[i] + add;
    g_off[i]    = excl;
    g_end[i]   += add;
    g_cursor[i] = excl;
}

// ---------------- 5: CSR fill (src, coeff) grouped by destination -------------
__global__ void k_fill(const void* __restrict__ eiv) {
    int e = blockIdx.x * blockDim.x + threadIdx.x;
    if (e >= N_EDGES) return;
    int s, d;
    load_edge(eiv, e, s, d);
    float c = g_dinv[s] * g_dinv[d];
    int pos = atomicAdd(&g_cursor[d], 1);
    g_csr[pos] = make_int2(s, __float_as_int(c));
}

// ---------------- 6/7: hop: 16 lanes/row, 2 edges in flight, NO shuffles ------
// Lane owns 4 features (uint2 of 2 half2). Half-warp eh = lane>>4 processes
// edges beg+eh, beg+eh+2, ... Metadata comes from a broadcast LDG (same addr
// across the half-warp) instead of shfl, so the md loads are pure induction
// addresses ptxas can front-batch: 4 independent gather chains in flight.
template <bool OUT_HALF>
__global__ void k_hop(const uint2* __restrict__ in, void* __restrict__ outv) {
    int warp = (blockIdx.x * blockDim.x + threadIdx.x) >> 5;
    if (warp >= N_NODES) return;
    int lane = threadIdx.x & 31;
    int fl   = lane & 15;        // 8B slot within the 128B row
    int eh   = lane >> 4;        // which edge of the pair

    int beg = g_off[warp];
    int end = g_end[warp];
    float di = g_dinv[warp];
    float sl = di * di;          // self-loop coefficient

    float2 accA = make_float2(0.f, 0.f);
    float2 accB = make_float2(0.f, 0.f);
    if (eh == 0) {               // self-loop term, counted once
        uint2 rs = __ldg(&in[warp * 16 + fl]);
        float2 s0 = __half22float2(*reinterpret_cast<const __half2*>(&rs.x));
        float2 s1 = __half22float2(*reinterpret_cast<const __half2*>(&rs.y));
        accA = make_float2(sl * s0.x, sl * s0.y);
        accB = make_float2(sl * s1.x, sl * s1.y);
    }

    #pragma unroll 4
    for (int e = beg + eh; e < end; e += 2) {
        int2 md = __ldg(&g_csr[e]);            // broadcast within half-warp
        float ci = __int_as_float(md.y);
        uint2 r = __ldg(&in[md.x * 16 + fl]);  // one 128B row per half-warp
        float2 lo = __half22float2(*reinterpret_cast<const __half2*>(&r.x));
        float2 hi = __half22float2(*reinterpret_cast<const __half2*>(&r.y));
        accA.x = fmaf(ci, lo.x, accA.x);
        accA.y = fmaf(ci, lo.y, accA.y);
        accB.x = fmaf(ci, hi.x, accB.x);
        accB.y = fmaf(ci, hi.y, accB.y);
    }

    // combine edge halves
    accA.x += __shfl_xor_sync(0xffffffffu, accA.x, 16);
    accA.y += __shfl_xor_sync(0xffffffffu, accA.y, 16);
    accB.x += __shfl_xor_sync(0xffffffffu, accB.x, 16);
    accB.y += __shfl_xor_sync(0xffffffffu, accB.y, 16);

    if (eh == 0) {
        if (OUT_HALF) {
            uint2 o;
            *reinterpret_cast<__half2*>(&o.x) = __floats2half2_rn(accA.x, accA.y);
            *reinterpret_cast<__half2*>(&o.y) = __floats2half2_rn(accB.x, accB.y);
            ((uint2*)outv)[warp * 16 + fl] = o;
        } else {
            ((float4*)outv)[warp * 16 + fl] =
                make_float4(accA.x, accA.y, accB.x, accB.y);
        }
    }
}

// ---------------- 8: out = relu(h2 @ W^T + b), packed f32x2 FMA ---------------
__global__ void __launch_bounds__(128) k_linear_relu(
        const float* __restrict__ h, const float* __restrict__ W,
        const float* __restrict__ b, float* __restrict__ out) {
    __shared__ float4 Ws4[D * 16];   // W[o][k] as float4 over k
    __shared__ float bs[D];
    for (int i = threadIdx.x; i < D * 16; i += blockDim.x)
        Ws4[i] = ((const float4*)W)[i];
    for (int i = threadIdx.x; i < D; i += blockDim.x) bs[i] = b[i];
    __syncthreads();

    int n = blockIdx.x * blockDim.x + threadIdx.x;
    if (n >= N_NODES) return;

    unsigned long long acc[D];
    #pragma unroll
    for (int o = 0; o < D; o++) PACK2(acc[o], bs[o], 0.0f);

    const float4* hr = (const float4*)(h + n * D);
    #pragma unroll 2
    for (int k4 = 0; k4 < 16; k4++) {
        float4 hv = hr[k4];
        unsigned long long h01, h23;
        PACK2(h01, hv.x, hv.y);
        PACK2(h23, hv.z, hv.w);
        #pragma unroll
        for (int o = 0; o < D; o++) {
            float4 w = Ws4[o * 16 + k4];
            unsigned long long w01, w23;
            PACK2(w01, w.x, w.y);
            PACK2(w23, w.z, w.w);
            FMA2(acc[o], h01, w01);
            FMA2(acc[o], h23, w23);
        }
    }
    float* orow = out + n * D;
    #pragma unroll
    for (int o = 0; o < D; o++) {
        float lo, hi;
        UNPACK2(lo, hi, acc[o]);
        orow[o] = fmaxf(lo + hi, 0.0f);
    }
}

// ---------------- launch ------------------------------------------------------
extern "C" void kernel_launch(void* const* d_in, const int* in_sizes, int n_in,
                              void* d_out, int out_size) {
    const float* x  = (const float*)d_in[0];   // [N, 64]
    const float* W  = (const float*)d_in[1];   // [64, 64]
    const float* b  = (const float*)d_in[2];   // [64]
    const void*  ei = d_in[3];                 // [2, E] int32 or int64
    float* out = (float*)d_out;                // [N, 64]

    void *xhp = nullptr, *h1p = nullptr, *h2p = nullptr;
    cudaGetSymbolAddress(&xhp, g_xh);
    cudaGetSymbolAddress(&h1p, g_h1h);
    cudaGetSymbolAddress(&h2p, g_h2);

    const int TB = 256;
    const int gBig = (N_NODES * 32 + TB - 1) / TB;   // 3.2M threads
    const int gE   = (N_EDGES + TB - 1) / TB;
    const int gN   = (N_NODES + TB - 1) / TB;
    const int gLin = (N_NODES + 127) / 128;

    k_init      <<<gBig, TB>>>((const unsigned int*)ei, (const float2*)x);
    k_pass1     <<<gE, TB>>>(ei);
    k_scan_local<<<NPART, SCAN_BLK>>>();
    k_finalize  <<<gN, TB>>>();
    k_fill      <<<gE, TB>>>(ei);

    // two hops: xh -> h1h (fp16) -> h2 (fp32); pure gather, no atomics
    k_hop<true> <<<gBig, TB>>>((const uint2*)xhp, h1p);
    k_hop<false><<<gBig, TB>>>((const uint2*)h1p, h2p);

    // out = relu(h2 @ W^T + b)
    k_linear_relu<<<gLin, 128>>>((const float*)h2p, W, b, out);
}